// round 1
// baseline (speedup 1.0000x reference)
#include <cuda_runtime.h>

// Net_2095944040841: 3-layer LSTM (with reference's buggy c-state wiring) on GB300.
// Persistent kernel: 128 CTAs x 4 batch elements, all weights in SMEM,
// linear1 fused into cell1 (Wc = Wih1 @ W1), f32x2 packed FMA over batch pairs.

#define T_LEN 1024
#define IN_D  20
#define HIDN  50
#define OUT_D 8
#define NB    4
#define NCTA  128
#define NTH   224

// shared memory layout (float offsets)
#define WA_STR 76          // cell1 row: 20 fused-x cols + 50 Whh1 cols + 6 pad
#define WA_OFF 0           // 200 x 76
#define WB_OFF 15200       // 200 x 100  [Wih2 | Whh2]
#define WC_OFF 35200       // 200 x 100  [Wih3 | Whh3]
#define BA_OFF 55200       // 200 fused bias cell1
#define BB_OFF 55400
#define BC_OFF 55600
#define W2_OFF 55800       // 8 x 50
#define B2_OFF 56200       // 8
#define IN1_OFF 56208      // 76 quads: [x_t(20) | h1(50) | pad(6)] x 4 batches
#define ST_OFF  56512      // 150 quads: h1(0..49) h2(50..99) h3(100..149)
#define ACT_OFF 57112      // 200 quads: activated gates
#define SMEM_FLT 57912     // 231,648 bytes

typedef unsigned long long ull;

static __device__ __forceinline__ ull pk2(float a) {
    ull r; asm("mov.b64 %0, {%1,%1};" : "=l"(r) : "f"(a)); return r;
}
static __device__ __forceinline__ void upk(ull v, float &a, float &b) {
    asm("mov.b64 {%0,%1}, %2;" : "=f"(a), "=f"(b) : "l"(v));
}
static __device__ __forceinline__ ull fma2(ull a, ull b, ull c) {
    ull d; asm("fma.rn.f32x2 %0, %1, %2, %3;" : "=l"(d) : "l"(a), "l"(b), "l"(c)); return d;
}
static __device__ __forceinline__ float sigm(float x) {
    return __fdividef(1.f, 1.f + __expf(-x));
}
static __device__ __forceinline__ float tanh_(float x) {
    x = fminf(fmaxf(x, -15.f), 15.f);
    float e = __expf(-2.f * x);
    return __fdividef(1.f - e, 1.f + e);
}

// One gate row r for 4 batch elements: dot(in[0..4*NQ), Wrow) + bias, then activation.
template<int NQ>
static __device__ __forceinline__ void cell_mv(const float* __restrict__ wrow, float bias,
                                               const float* __restrict__ in,
                                               float* __restrict__ actq, int r)
{
    const float4* w4p = reinterpret_cast<const float4*>(wrow);
    const ulonglong2* q = reinterpret_cast<const ulonglong2*>(in);
    ull a01 = pk2(bias), a23 = a01;
#pragma unroll
    for (int kk = 0; kk < NQ; kk++) {
        float4 w = w4p[kk];
        ulonglong2 q0 = q[4*kk+0], q1 = q[4*kk+1], q2 = q[4*kk+2], q3 = q[4*kk+3];
        ull w0 = pk2(w.x), w1 = pk2(w.y), w2 = pk2(w.z), w3 = pk2(w.w);
        a01 = fma2(w0, q0.x, a01); a23 = fma2(w0, q0.y, a23);
        a01 = fma2(w1, q1.x, a01); a23 = fma2(w1, q1.y, a23);
        a01 = fma2(w2, q2.x, a01); a23 = fma2(w2, q2.y, a23);
        a01 = fma2(w3, q3.x, a01); a23 = fma2(w3, q3.y, a23);
    }
    float g0, g1, g2, g3;
    upk(a01, g0, g1); upk(a23, g2, g3);
    if (r < 100 || r >= 150) {            // i, f, o gates -> sigmoid
        g0 = sigm(g0); g1 = sigm(g1); g2 = sigm(g2); g3 = sigm(g3);
    } else {                               // g gate -> tanh
        g0 = tanh_(g0); g1 = tanh_(g1); g2 = tanh_(g2); g3 = tanh_(g3);
    }
    reinterpret_cast<float4*>(actq)[r] = make_float4(g0, g1, g2, g3);
}

extern __shared__ float sm[];

__global__ void __launch_bounds__(NTH, 1)
lstm_persist_kernel(const float* __restrict__ x,
                    const float* __restrict__ W1,   const float* __restrict__ b1,
                    const float* __restrict__ Wih1, const float* __restrict__ Whh1,
                    const float* __restrict__ bih1, const float* __restrict__ bhh1,
                    const float* __restrict__ Wih2, const float* __restrict__ Whh2,
                    const float* __restrict__ bih2, const float* __restrict__ bhh2,
                    const float* __restrict__ Wih3, const float* __restrict__ Whh3,
                    const float* __restrict__ bih3, const float* __restrict__ bhh3,
                    const float* __restrict__ W2,   const float* __restrict__ b2,
                    float* __restrict__ out)
{
    const int tid = threadIdx.x;
    const int b0  = blockIdx.x * NB;

    // ---------------- init: build fused weights in SMEM ----------------
    // stage W1 (50x20 = 1000 floats) temporarily in the state/act region
    for (int i = tid; i < HIDN * IN_D; i += NTH) sm[ST_OFF + i] = W1[i];
    __syncthreads();

    // WA x-part: Wc[r][k] = sum_j Wih1[r][j] * W1[j][k]
    for (int i = tid; i < 200 * IN_D; i += NTH) {
        int r = i / IN_D, k = i % IN_D;
        float acc = 0.f;
#pragma unroll 10
        for (int j = 0; j < HIDN; j++)
            acc += Wih1[r * HIDN + j] * sm[ST_OFF + j * IN_D + k];
        sm[WA_OFF + r * WA_STR + k] = acc;
    }
    // WA h-part + zero pad
    for (int i = tid; i < 200 * 56; i += NTH) {
        int r = i / 56, c = i % 56;
        sm[WA_OFF + r * WA_STR + IN_D + c] = (c < HIDN) ? Whh1[r * HIDN + c] : 0.f;
    }
    // fused biases
    for (int r = tid; r < 200; r += NTH) {
        float acc = bih1[r] + bhh1[r];
#pragma unroll 10
        for (int j = 0; j < HIDN; j++) acc += Wih1[r * HIDN + j] * b1[j];
        sm[BA_OFF + r] = acc;
        sm[BB_OFF + r] = bih2[r] + bhh2[r];
        sm[BC_OFF + r] = bih3[r] + bhh3[r];
    }
    // WB = [Wih2 | Whh2], WC = [Wih3 | Whh3]
    for (int i = tid; i < 200 * 100; i += NTH) {
        int r = i / 100, c = i % 100;
        sm[WB_OFF + i] = (c < HIDN) ? Wih2[r * HIDN + c] : Whh2[r * HIDN + c - HIDN];
        sm[WC_OFF + i] = (c < HIDN) ? Wih3[r * HIDN + c] : Whh3[r * HIDN + c - HIDN];
    }
    for (int i = tid; i < OUT_D * HIDN; i += NTH) sm[W2_OFF + i] = W2[i];
    if (tid < OUT_D) sm[B2_OFF + tid] = b2[tid];
    __syncthreads();  // W1 staging reads complete before zeroing that region

    // zero state, act, and in1 (skip first 80 slots of in1: x(0) goes there)
    for (int i = 80 + tid; i < 304; i += NTH) sm[IN1_OFF + i] = 0.f;
    for (int i = tid; i < 600; i += NTH) sm[ST_OFF + i] = 0.f;
    for (int i = tid; i < 800; i += NTH) sm[ACT_OFF + i] = 0.f;
    // load x(0) into in1 quads [k][b]
    if (tid < NB * IN_D) {
        int b = tid / IN_D, k = tid % IN_D;
        sm[IN1_OFF + k * NB + b] = x[((size_t)(b0 + b) * T_LEN) * IN_D + k];
    }
    __syncthreads();

    // ---------------- main recurrent loop ----------------
    const int r  = tid;
    const int xb = tid / IN_D, xk = tid % IN_D;
    const bool isx = (tid < NB * IN_D);

    // per-hidden-unit cell states (threads tid<50 only); c3 is always 0 (ref bug),
    // cz carries "c2" which is overwritten each step by cell3's c_new.
    float c1s[NB] = {0.f, 0.f, 0.f, 0.f};
    float czs[NB] = {0.f, 0.f, 0.f, 0.f};

    for (int t = 0; t < T_LEN; t++) {
        // prefetch x(t+1)
        float xv = 0.f;
        const bool xl = isx && (t + 1 < T_LEN);
        if (xl) xv = x[((size_t)(b0 + xb) * T_LEN + (t + 1)) * IN_D + xk];

        // ---- cell 1: gates from [x_t | h1] ----
        if (r < 200)
            cell_mv<19>(sm + WA_OFF + r * WA_STR, sm[BA_OFF + r],
                        sm + IN1_OFF, sm + ACT_OFF, r);
        __syncthreads();

        // ---- update 1 (+ store x(t+1)) ----
        if (r < HIDN) {
            float4 iq = reinterpret_cast<float4*>(sm + ACT_OFF)[r];
            float4 fq = reinterpret_cast<float4*>(sm + ACT_OFF)[50 + r];
            float4 gq = reinterpret_cast<float4*>(sm + ACT_OFF)[100 + r];
            float4 oq = reinterpret_cast<float4*>(sm + ACT_OFF)[150 + r];
            float h[NB];
            c1s[0] = fq.x * c1s[0] + iq.x * gq.x;  h[0] = oq.x * tanh_(c1s[0]);
            c1s[1] = fq.y * c1s[1] + iq.y * gq.y;  h[1] = oq.y * tanh_(c1s[1]);
            c1s[2] = fq.z * c1s[2] + iq.z * gq.z;  h[2] = oq.z * tanh_(c1s[2]);
            c1s[3] = fq.w * c1s[3] + iq.w * gq.w;  h[3] = oq.w * tanh_(c1s[3]);
            float4 hv = make_float4(h[0], h[1], h[2], h[3]);
            reinterpret_cast<float4*>(sm + ST_OFF)[r] = hv;            // h1 for cell2
            reinterpret_cast<float4*>(sm + IN1_OFF)[IN_D + r] = hv;    // h1 for next cell1
        }
        if (xl) sm[IN1_OFF + xk * NB + xb] = xv;
        __syncthreads();

        // ---- cell 2: gates from [h1 | h2] ----
        if (r < 200)
            cell_mv<25>(sm + WB_OFF + r * 100, sm[BB_OFF + r],
                        sm + ST_OFF, sm + ACT_OFF, r);
        __syncthreads();

        // ---- update 2: uses cz (cell3's c_new from previous step) as cell state ----
        if (r < HIDN) {
            float4 iq = reinterpret_cast<float4*>(sm + ACT_OFF)[r];
            float4 fq = reinterpret_cast<float4*>(sm + ACT_OFF)[50 + r];
            float4 gq = reinterpret_cast<float4*>(sm + ACT_OFF)[100 + r];
            float4 oq = reinterpret_cast<float4*>(sm + ACT_OFF)[150 + r];
            float c2t, h[NB];
            c2t = fq.x * czs[0] + iq.x * gq.x;  h[0] = oq.x * tanh_(c2t);
            c2t = fq.y * czs[1] + iq.y * gq.y;  h[1] = oq.y * tanh_(c2t);
            c2t = fq.z * czs[2] + iq.z * gq.z;  h[2] = oq.z * tanh_(c2t);
            c2t = fq.w * czs[3] + iq.w * gq.w;  h[3] = oq.w * tanh_(c2t);
            reinterpret_cast<float4*>(sm + ST_OFF)[50 + r] =
                make_float4(h[0], h[1], h[2], h[3]);                   // h2
        }
        __syncthreads();

        // ---- cell 3: gates from [h2 | h3]; c3 input is always 0 ----
        if (r < 200)
            cell_mv<25>(sm + WC_OFF + r * 100, sm[BC_OFF + r],
                        sm + ST_OFF + 50 * NB, sm + ACT_OFF, r);
        __syncthreads();

        // ---- update 3: c_new = i*g (f*0 dropped); cz <- c_new ----
        if (r < HIDN) {
            float4 iq = reinterpret_cast<float4*>(sm + ACT_OFF)[r];
            float4 gq = reinterpret_cast<float4*>(sm + ACT_OFF)[100 + r];
            float4 oq = reinterpret_cast<float4*>(sm + ACT_OFF)[150 + r];
            float h[NB];
            czs[0] = iq.x * gq.x;  h[0] = oq.x * tanh_(czs[0]);
            czs[1] = iq.y * gq.y;  h[1] = oq.y * tanh_(czs[1]);
            czs[2] = iq.z * gq.z;  h[2] = oq.z * tanh_(czs[2]);
            czs[3] = iq.w * gq.w;  h[3] = oq.w * tanh_(czs[3]);
            reinterpret_cast<float4*>(sm + ST_OFF)[100 + r] =
                make_float4(h[0], h[1], h[2], h[3]);                   // h3
        }
        __syncthreads();

        // ---- output projection: out[b][t][o] = h3 @ W2.T + b2 ----
        if (tid < NB * OUT_D) {
            int b = tid >> 3, o = tid & 7;
            float acc = sm[B2_OFF + o];
#pragma unroll
            for (int j = 0; j < HIDN; j++)
                acc += sm[W2_OFF + o * HIDN + j] * sm[ST_OFF + (100 + j) * NB + b];
            out[((size_t)(b0 + b) * T_LEN + t) * OUT_D + o] = acc;
        }
        // no sync needed: nothing below reads 'out'; h3 is protected by the
        // 5 barriers before next step's update3.
    }
}

extern "C" void kernel_launch(void* const* d_in, const int* in_sizes, int n_in,
                              void* d_out, int out_size)
{
    const float* x    = (const float*)d_in[0];
    const float* W1   = (const float*)d_in[1];
    const float* b1   = (const float*)d_in[2];
    const float* Wih1 = (const float*)d_in[3];
    const float* Whh1 = (const float*)d_in[4];
    const float* bih1 = (const float*)d_in[5];
    const float* bhh1 = (const float*)d_in[6];
    const float* Wih2 = (const float*)d_in[7];
    const float* Whh2 = (const float*)d_in[8];
    const float* bih2 = (const float*)d_in[9];
    const float* bhh2 = (const float*)d_in[10];
    const float* Wih3 = (const float*)d_in[11];
    const float* Whh3 = (const float*)d_in[12];
    const float* bih3 = (const float*)d_in[13];
    const float* bhh3 = (const float*)d_in[14];
    const float* W2   = (const float*)d_in[15];
    const float* b2   = (const float*)d_in[16];
    float* out = (float*)d_out;

    const int smem_bytes = SMEM_FLT * sizeof(float);  // 231,648
    cudaFuncSetAttribute(lstm_persist_kernel,
                         cudaFuncAttributeMaxDynamicSharedMemorySize, smem_bytes);

    lstm_persist_kernel<<<NCTA, NTH, smem_bytes>>>(
        x, W1, b1, Wih1, Whh1, bih1, bhh1,
        Wih2, Whh2, bih2, bhh2, Wih3, Whh3, bih3, bhh3,
        W2, b2, out);
}